// round 3
// baseline (speedup 1.0000x reference)
#include <cuda_runtime.h>

// ---------------- problem constants ----------------
#define NN    4000        // nodes
#define LL    15000       // sequence length
#define NW    1000        // LL/15 windows
#define EE    128000      // raw edges
#define ETOT  (EE + NN)   // + self loops
#define HEADS 8
#define NHID  64
#define FDIM  512         // HEADS*NHID
#define GHD   64
#define NEGS  0.2f
#define CHUNK 1024        // M-chunk for conv/gemm pipeline

// ---------------- device scratch (no allocs allowed) ----------------
__device__ float g_h[NN * NW];        // conv output  [4000,1000]  16MB
__device__ float g_gf[NN * GHD];      // geneflow fc1 [4000,64]
__device__ float g_ag[NN * HEADS];    // per-node gene-attn dots
__device__ float g_xl[NN * FDIM];     // h @ W1 + b1  [4000,512]   8MB
__device__ float g_af[NN * HEADS];    // per-node feat-attn dots
__device__ int   g_cnt[NN];           // histogram / cursor
__device__ int   g_rowptr[NN + 1];    // CSR by dst
__device__ int   g_srcs[ETOT];        // src ids sorted by dst
__device__ float g_xl2[NN];           // layer-2 feature scalar (h1@W2+b2)
__device__ float g_gf2[NN];           // layer-2 gene scalar

__device__ __forceinline__ float lrelu(float v) { return v > 0.f ? v : NEGS * v; }

__device__ __forceinline__ void fma2(unsigned long long& d, unsigned long long a,
                                     unsigned long long b) {
    asm("fma.rn.f32x2 %0, %1, %2, %0;" : "+l"(d) : "l"(a), "l"(b));
}
__device__ __forceinline__ unsigned long long packrep(float v) {
    unsigned long long o;
    asm("mov.b64 %0, {%1, %1};" : "=l"(o) : "f"(v));
    return o;
}
__device__ __forceinline__ float2 unpack2(unsigned long long v) {
    float2 r;
    asm("mov.b64 {%0, %1}, %2;" : "=f"(r.x), "=f"(r.y) : "l"(v));
    return r;
}

// ---------------- fused Conv1d(4->1,k=1) + Conv1d(1->1,k=15,s=15) ----------------
// grid (5, chunkN), block 256. Each block: 200 windows = 3000 L-elements.
__global__ void k_conv(const float4* __restrict__ x4, int nOff,
                       const float* __restrict__ cjw, const float* __restrict__ cjb,
                       const float* __restrict__ cj2w, const float* __restrict__ cj2b) {
    __shared__ __align__(16) float sm[3000];
    int n = nOff + blockIdx.y, seg = blockIdx.x, tid = threadIdx.x;
    float w0 = cjw[0], w1 = cjw[1], w2 = cjw[2], w3 = cjw[3];
    const float4* xr = x4 + (size_t)n * (4 * 3750) + seg * 750;
    for (int i = tid; i < 750; i += 256) {
        float4 a = __ldcs(xr + i);
        float4 b = __ldcs(xr + 3750 + i);
        float4 c = __ldcs(xr + 7500 + i);
        float4 d = __ldcs(xr + 11250 + i);
        float4 v;
        v.x = a.x * w0 + b.x * w1 + c.x * w2 + d.x * w3;
        v.y = a.y * w0 + b.y * w1 + c.y * w2 + d.y * w3;
        v.z = a.z * w0 + b.z * w1 + c.z * w2 + d.z * w3;
        v.w = a.w * w0 + b.w * w1 + c.w * w2 + d.w * w3;
        *(float4*)&sm[i * 4] = v;
    }
    __syncthreads();
    if (tid < 200) {
        float acc = 0.f, ws = 0.f;
#pragma unroll
        for (int k = 0; k < 15; k++) {
            float wk = cj2w[k];
            ws += wk;
            acc += sm[tid * 15 + k] * wk;
        }
        g_h[n * NW + seg * 200 + tid] = acc + cjb[0] * ws + cj2b[0];
    }
}

// ---------------- geneflow fc1 + per-node gene attention dots ----------------
__global__ void k_gf(const float* __restrict__ gfin, const float* __restrict__ fc1w,
                     const float* __restrict__ fc1b, const float* __restrict__ att1g) {
    __shared__ float gin[64], gout[64];
    int n = blockIdx.x, t = threadIdx.x;
    gin[t] = gfin[n * 64 + t];
    __syncthreads();
    float acc = fc1b[t];
#pragma unroll 8
    for (int i = 0; i < 64; i++) acc += gin[i] * fc1w[i * GHD + t];
    g_gf[n * GHD + t] = acc;
    gout[t] = acc;
    __syncthreads();
    if (t < HEADS) {
        float a = 0.f;
#pragma unroll 8
        for (int g = 0; g < GHD; g++) a += gout[g] * att1g[t * GHD + g];
        g_ag[n * HEADS + t] = a;
    }
}

// ---------------- GEMM: xl = h[rows] @ W1[1000,512] + b1, fused af epilogue ----
// BM=64 BN=128 BK=8, 256 threads, 4x8 reg tile via f32x2 packed FMA. grid (16, 4).
#define AS_STRIDE 68
__global__ void __launch_bounds__(256, 2) k_gemm1(const float* __restrict__ W1,
                                                  const float* __restrict__ b1,
                                                  const float* __restrict__ att1f,
                                                  int rowOff, int rowEnd) {
    __shared__ __align__(16) float As[8 * AS_STRIDE];
    __shared__ __align__(16) float Bs[8 * 128];
    int tid = threadIdx.x;
    int bm0 = rowOff + blockIdx.x * 64, bn0 = blockIdx.y * 128;
    int tm = tid >> 4, tn = tid & 15;

    int aRow = tid >> 2, aK = (tid & 3) * 2;
    int bK = tid >> 5, bC = (tid & 31) * 4;
    bool aValid = (bm0 + aRow) < rowEnd;
    const float* Aptr = g_h + (bm0 + aRow) * NW + aK;
    const float* Bptr = W1 + bK * FDIM + bn0 + bC;

    unsigned long long acc[4][4];
#pragma unroll
    for (int i = 0; i < 4; i++)
#pragma unroll
        for (int j = 0; j < 4; j++) acc[i][j] = 0ull;

    float2 areg = make_float2(0.f, 0.f);
    if (aValid) areg = *(const float2*)Aptr;
    float4 breg = *(const float4*)Bptr;

    for (int kt = 0; kt < 125; kt++) {
        As[(aK + 0) * AS_STRIDE + aRow] = areg.x;
        As[(aK + 1) * AS_STRIDE + aRow] = areg.y;
        *(float4*)&Bs[bK * 128 + bC] = breg;
        __syncthreads();
        if (kt < 124) {
            if (aValid) areg = *(const float2*)(Aptr + (kt + 1) * 8);
            breg = *(const float4*)(Bptr + (kt + 1) * 8 * FDIM);
        }
#pragma unroll
        for (int k = 0; k < 8; k++) {
            float4 av = *(const float4*)&As[k * AS_STRIDE + tm * 4];
            ulonglong2 b01 = *(const ulonglong2*)&Bs[k * 128 + tn * 8];
            ulonglong2 b23 = *(const ulonglong2*)&Bs[k * 128 + tn * 8 + 4];
            unsigned long long a0 = packrep(av.x), a1 = packrep(av.y);
            unsigned long long a2 = packrep(av.z), a3 = packrep(av.w);
            fma2(acc[0][0], a0, b01.x); fma2(acc[0][1], a0, b01.y);
            fma2(acc[0][2], a0, b23.x); fma2(acc[0][3], a0, b23.y);
            fma2(acc[1][0], a1, b01.x); fma2(acc[1][1], a1, b01.y);
            fma2(acc[1][2], a1, b23.x); fma2(acc[1][3], a1, b23.y);
            fma2(acc[2][0], a2, b01.x); fma2(acc[2][1], a2, b01.y);
            fma2(acc[2][2], a2, b23.x); fma2(acc[2][3], a2, b23.y);
            fma2(acc[3][0], a3, b01.x); fma2(acc[3][1], a3, b01.y);
            fma2(acc[3][2], a3, b23.x); fma2(acc[3][3], a3, b23.y);
        }
        __syncthreads();
    }

    // epilogue: + b1, store xl, fused per-head attention dot af
    int row0 = bm0 + tm * 4;
    float afp[4] = {0.f, 0.f, 0.f, 0.f};
#pragma unroll
    for (int i = 0; i < 4; i++) {
        int m = row0 + i;
        bool ok = m < rowEnd;
#pragma unroll
        for (int jp = 0; jp < 4; jp++) {
            int c0 = bn0 + tn * 8 + 2 * jp;
            float2 v = unpack2(acc[i][jp]);
            float o0 = v.x + b1[c0], o1 = v.y + b1[c0 + 1];
            if (ok) *(float2*)&g_xl[m * FDIM + c0] = make_float2(o0, o1);
            afp[i] += o0 * att1f[c0] + o1 * att1f[c0 + 1];
        }
    }
#pragma unroll
    for (int i = 0; i < 4; i++) {
        afp[i] += __shfl_down_sync(0xffffffffu, afp[i], 4);
        afp[i] += __shfl_down_sync(0xffffffffu, afp[i], 2);
        afp[i] += __shfl_down_sync(0xffffffffu, afp[i], 1);
    }
    if ((tn & 7) == 0) {
        int head = blockIdx.y * 2 + (tn >> 3);
#pragma unroll
        for (int i = 0; i < 4; i++) {
            int m = row0 + i;
            if (m < rowEnd) g_af[m * 8 + head] = afp[i];
        }
    }
}

// ---------------- CSR build ----------------
__global__ void k_init() {
    int i = blockIdx.x * blockDim.x + threadIdx.x;
    if (i < NN) g_cnt[i] = 1;  // self loop
}
__global__ void k_hist(const int* __restrict__ ei) {
    int e = blockIdx.x * blockDim.x + threadIdx.x;
    if (e < EE) atomicAdd(&g_cnt[ei[EE + e]], 1);
}
__global__ void k_scan() {  // 1 block, 1024 threads, 4 elems each
    __shared__ int sums[1024];
    int tid = threadIdx.x;
    int base = tid * 4;
    int v0 = 0, v1 = 0, v2 = 0, v3 = 0;
    if (base + 0 < NN) v0 = g_cnt[base + 0];
    if (base + 1 < NN) v1 = g_cnt[base + 1];
    if (base + 2 < NN) v2 = g_cnt[base + 2];
    if (base + 3 < NN) v3 = g_cnt[base + 3];
    sums[tid] = v0 + v1 + v2 + v3;
    __syncthreads();
    for (int off = 1; off < 1024; off <<= 1) {
        int add = (tid >= off) ? sums[tid - off] : 0;
        __syncthreads();
        sums[tid] += add;
        __syncthreads();
    }
    int run = tid ? sums[tid - 1] : 0;
    if (base + 0 < NN) { g_rowptr[base + 0] = run; g_cnt[base + 0] = run; run += v0; }
    if (base + 1 < NN) { g_rowptr[base + 1] = run; g_cnt[base + 1] = run; run += v1; }
    if (base + 2 < NN) { g_rowptr[base + 2] = run; g_cnt[base + 2] = run; run += v2; }
    if (base + 3 < NN) { g_rowptr[base + 3] = run; g_cnt[base + 3] = run; run += v3; }
    if (tid == 1023) g_rowptr[NN] = sums[1023];
}
__global__ void k_scatter(const int* __restrict__ ei) {
    int e = blockIdx.x * blockDim.x + threadIdx.x;
    if (e >= ETOT) return;
    int s, d;
    if (e < EE) { s = ei[e]; d = ei[EE + e]; }
    else        { s = d = e - EE; }
    int p = atomicAdd(&g_cnt[d], 1);
    g_srcs[p] = s;
}

// ---------------- layer-1 attention + aggregation + fused epilogue ----------------
__global__ void __launch_bounds__(512) k_agg1(
    const float* __restrict__ bias1f, const float* __restrict__ bias1g,
    const float* __restrict__ W2, const float* __restrict__ b2,
    const float* __restrict__ fc2w, const float* __restrict__ fc2b) {
    __shared__ float afn[8], agn[8], m1s[8], i1s[8], m2s[8], i2s[8];
    __shared__ int   ssrc[128];
    __shared__ float w2s[128 * 8];
    __shared__ float abars[128];
    __shared__ float red[16];

    int n = blockIdx.x, t = threadIdx.x;
    int base = g_rowptr[n];
    int deg  = g_rowptr[n + 1] - base;
    int w = t >> 5, lane = t & 31;

    if (t < 8) { afn[t] = g_af[n * 8 + t]; agn[t] = g_ag[n * 8 + t]; }
    __syncthreads();

    // pass 1: per-head softmax max & sum (warps 0..7 = heads)
    if (w < 8) {
        int h = w;
        float an = afn[h], gn = agn[h];
        float m1 = -1e30f, m2 = -1e30f;
        for (int e = lane; e < deg; e += 32) {
            int s = g_srcs[base + e];
            float v1 = lrelu(an + g_af[s * 8 + h]);
            float v2 = lrelu(gn + g_ag[s * 8 + h]);
            m1 = fmaxf(m1, v1); m2 = fmaxf(m2, v2);
        }
#pragma unroll
        for (int off = 16; off; off >>= 1) {
            m1 = fmaxf(m1, __shfl_xor_sync(0xffffffffu, m1, off));
            m2 = fmaxf(m2, __shfl_xor_sync(0xffffffffu, m2, off));
        }
        float s1 = 0.f, s2 = 0.f;
        for (int e = lane; e < deg; e += 32) {
            int s = g_srcs[base + e];
            float v1 = lrelu(an + g_af[s * 8 + h]);
            float v2 = lrelu(gn + g_ag[s * 8 + h]);
            s1 += __expf(v1 - m1); s2 += __expf(v2 - m2);
        }
#pragma unroll
        for (int off = 16; off; off >>= 1) {
            s1 += __shfl_xor_sync(0xffffffffu, s1, off);
            s2 += __shfl_xor_sync(0xffffffffu, s2, off);
        }
        if (lane == 0) { m1s[h] = m1; i1s[h] = 1.f / s1; m2s[h] = m2; i2s[h] = 1.f / s2; }
    }
    __syncthreads();

    // pass 2: chunked weighted aggregation
    int h = t >> 6, c = t & 63;
    float accf = 0.f, accg = 0.f;
    for (int c0 = 0; c0 < deg; c0 += 128) {
        int clen = min(128, deg - c0);
        if (t < clen) ssrc[t] = g_srcs[base + c0 + t];
        __syncthreads();
        if (t < clen) {
            int s = ssrc[t];
            float ab = 0.f;
#pragma unroll
            for (int hh = 0; hh < 8; hh++) {
                float v1 = lrelu(afn[hh] + g_af[s * 8 + hh]);
                ab += __expf(v1 - m1s[hh]) * i1s[hh];
                float v2 = lrelu(agn[hh] + g_ag[s * 8 + hh]);
                w2s[t * 8 + hh] = __expf(v2 - m2s[hh]) * i2s[hh];
            }
            abars[t] = ab * 0.125f;
        }
        __syncthreads();
        if (h == 0) {
#pragma unroll 4
            for (int e = 0; e < clen; e++) {
                int s = ssrc[e];
                accf += w2s[e * 8] * g_xl[s * FDIM + t];
                accg += abars[e] * g_gf[s * GHD + c];
            }
        } else {
#pragma unroll 4
            for (int e = 0; e < clen; e++) {
                int s = ssrc[e];
                accf += w2s[e * 8 + h] * g_xl[s * FDIM + t];
            }
        }
        __syncthreads();
    }

    // epilogue: relu + h1@W2+b2 (block reduce) ; relu(g)+fc2 (64-thread reduce)
    float o = fmaxf(accf + bias1f[t], 0.f);
    float v = o * W2[t];
#pragma unroll
    for (int off = 16; off; off >>= 1) v += __shfl_down_sync(0xffffffffu, v, off);
    if (lane == 0) red[w] = v;
    __syncthreads();
    if (t < 16) {
        float r = red[t];
#pragma unroll
        for (int off = 8; off; off >>= 1) r += __shfl_down_sync(0x0000ffffu, r, off);
        if (t == 0) g_xl2[n] = r + b2[0];
    }
    float gv = 0.f;
    if (t < 64) {
        float g1 = fmaxf(accg + bias1g[t], 0.f);
        gv = g1 * fc2w[t];
#pragma unroll
        for (int off = 16; off; off >>= 1) gv += __shfl_down_sync(0xffffffffu, gv, off);
    }
    __syncthreads();
    if (t < 64 && lane == 0) red[w] = gv;
    __syncthreads();
    if (t == 0) g_gf2[n] = red[0] + red[1] + fc2b[0];
}

// ---------------- layer 2 (heads=1, C=1) + final sigmoid, warp per node ----------------
__global__ void k_agg2(float* __restrict__ out,
                       const float* __restrict__ att2f, const float* __restrict__ att2g,
                       const float* __restrict__ bias2f, const float* __restrict__ bias2g) {
    int gwarp = (blockIdx.x * blockDim.x + threadIdx.x) >> 5;
    int lane = threadIdx.x & 31;
    if (gwarp >= NN) return;
    int n = gwarp;
    float taf = att2f[0], tag = att2g[0];
    int base = g_rowptr[n], deg = g_rowptr[n + 1] - base;
    float xn = g_xl2[n], gn = g_gf2[n];
    float m1 = -1e30f, m2 = -1e30f;
    for (int e = lane; e < deg; e += 32) {
        int s = g_srcs[base + e];
        float v1 = lrelu(taf * (xn + g_xl2[s]));
        float v2 = lrelu(tag * (gn + g_gf2[s]));
        m1 = fmaxf(m1, v1); m2 = fmaxf(m2, v2);
    }
#pragma unroll
    for (int off = 16; off; off >>= 1) {
        m1 = fmaxf(m1, __shfl_xor_sync(0xffffffffu, m1, off));
        m2 = fmaxf(m2, __shfl_xor_sync(0xffffffffu, m2, off));
    }
    float s1 = 0.f, s2 = 0.f, hf = 0.f, hg = 0.f;
    for (int e = lane; e < deg; e += 32) {
        int s = g_srcs[base + e];
        float xs = g_xl2[s], gs = g_gf2[s];
        float v1 = lrelu(taf * (xn + xs));
        float v2 = lrelu(tag * (gn + gs));
        float e1 = __expf(v1 - m1), e2 = __expf(v2 - m2);
        s1 += e1; s2 += e2;
        hf += e2 * xs;
        hg += e1 * gs;
    }
#pragma unroll
    for (int off = 16; off; off >>= 1) {
        s1 += __shfl_xor_sync(0xffffffffu, s1, off);
        s2 += __shfl_xor_sync(0xffffffffu, s2, off);
        hf += __shfl_xor_sync(0xffffffffu, hf, off);
        hg += __shfl_xor_sync(0xffffffffu, hg, off);
    }
    if (lane == 0) {
        float h2  = hf / s2 + bias2f[0];
        float gf3 = hg / s1 + bias2g[0];
        float z = h2 + gf3;
        out[n] = 1.f / (1.f + __expf(-z));
    }
}

// ---------------- launcher: forked two-stream pipeline inside graph capture ------
extern "C" void kernel_launch(void* const* d_in, const int* in_sizes, int n_in,
                              void* d_out, int out_size) {
    const float* x      = (const float*)d_in[0];
    const float* gfin   = (const float*)d_in[1];
    const int*   ei     = (const int*)d_in[2];
    const float* cjw    = (const float*)d_in[3];
    const float* cjb    = (const float*)d_in[4];
    const float* cj2w   = (const float*)d_in[5];
    const float* cj2b   = (const float*)d_in[6];
    const float* fc1w   = (const float*)d_in[7];
    const float* fc1b   = (const float*)d_in[8];
    const float* fc2w   = (const float*)d_in[9];
    const float* fc2b   = (const float*)d_in[10];
    const float* W1     = (const float*)d_in[11];
    const float* b1     = (const float*)d_in[12];
    const float* att1f  = (const float*)d_in[13];
    const float* att1g  = (const float*)d_in[14];
    const float* bias1f = (const float*)d_in[15];
    const float* bias1g = (const float*)d_in[16];
    const float* W2     = (const float*)d_in[17];
    const float* b2     = (const float*)d_in[18];
    const float* att2f  = (const float*)d_in[19];
    const float* att2g  = (const float*)d_in[20];
    const float* bias2f = (const float*)d_in[21];
    const float* bias2g = (const float*)d_in[22];
    float* out = (float*)d_out;

    cudaStream_t sB;
    cudaStreamCreateWithFlags(&sB, cudaStreamNonBlocking);
    cudaEvent_t evFork, evJoin, evC[4];
    cudaEventCreateWithFlags(&evFork, cudaEventDisableTiming);
    cudaEventCreateWithFlags(&evJoin, cudaEventDisableTiming);
    for (int c = 0; c < 4; c++) cudaEventCreateWithFlags(&evC[c], cudaEventDisableTiming);

    // fork side stream off the capturing default stream
    cudaEventRecord(evFork, 0);
    cudaStreamWaitEvent(sB, evFork, 0);

    // stream B: CSR build + geneflow fc1 (independent of conv)
    k_init<<<(NN + 255) / 256, 256, 0, sB>>>();
    k_hist<<<(EE + 255) / 256, 256, 0, sB>>>(ei);
    k_scan<<<1, 1024, 0, sB>>>();
    k_scatter<<<(ETOT + 255) / 256, 256, 0, sB>>>(ei);
    k_gf<<<NN, 64, 0, sB>>>(gfin, fc1w, fc1b, att1g);

    // main stream: conv chunks; stream B: gemm chunk i after conv chunk i
    int offs[5] = {0, CHUNK, 2 * CHUNK, 3 * CHUNK, NN};
    for (int c = 0; c < 4; c++) {
        int off = offs[c], end = offs[c + 1];
        k_conv<<<dim3(5, end - off), 256>>>((const float4*)x, off, cjw, cjb, cj2w, cj2b);
        cudaEventRecord(evC[c], 0);
        cudaStreamWaitEvent(sB, evC[c], 0);
        k_gemm1<<<dim3(16, 4), 256, 0, sB>>>(W1, b1, att1f, off, end);
    }

    // graph layers (stream B, after all gemm + CSR + gf in stream order)
    k_agg1<<<NN, 512, 0, sB>>>(bias1f, bias1g, W2, b2, fc2w, fc2b);
    k_agg2<<<(NN * 32 + 255) / 256, 256, 0, sB>>>(out, att2f, att2g, bias2f, bias2g);

    // join back to the capturing stream
    cudaEventRecord(evJoin, sB);
    cudaStreamWaitEvent(0, evJoin, 0);
}

// round 4
// speedup vs baseline: 2.4226x; 2.4226x over previous
#include <cuda_runtime.h>
#include <cstdint>

// ---------------- problem constants ----------------
#define NN    4000        // nodes
#define LL    15000       // sequence length
#define NW    1000        // LL/15 windows
#define EE    128000      // raw edges
#define ETOT  (EE + NN)   // + self loops
#define HEADS 8
#define NHID  64
#define FDIM  512         // HEADS*NHID
#define GHD   64
#define NEGS  0.2f

// ---------------- device scratch (no allocs allowed) ----------------
__device__ float g_gf[NN * GHD];      // geneflow fc1 [4000,64]
__device__ float g_ag[NN * HEADS];    // per-node gene-attn dots
__device__ float g_xl[NN * FDIM];     // conv->gemm output [4000,512]
__device__ float g_af[NN * HEADS];    // per-node feat-attn dots
__device__ int   g_cnt[NN];           // histogram / cursor
__device__ int   g_rowptr[NN + 1];    // CSR by dst
__device__ int   g_srcs[ETOT];        // src ids sorted by dst
__device__ float g_xl2[NN];           // layer-2 feature scalar
__device__ float g_gf2[NN];           // layer-2 gene scalar

__device__ __forceinline__ float lrelu(float v) { return v > 0.f ? v : NEGS * v; }

__device__ __forceinline__ void fma2(unsigned long long& d, unsigned long long a,
                                     unsigned long long b) {
    asm("fma.rn.f32x2 %0, %1, %2, %0;" : "+l"(d) : "l"(a), "l"(b));
}
__device__ __forceinline__ unsigned long long packrep(float v) {
    unsigned long long o;
    asm("mov.b64 %0, {%1, %1};" : "=l"(o) : "f"(v));
    return o;
}
__device__ __forceinline__ float2 unpack2(unsigned long long v) {
    float2 r;
    asm("mov.b64 {%0, %1}, %2;" : "=f"(r.x), "=f"(r.y) : "l"(v));
    return r;
}
__device__ __forceinline__ unsigned su32(const void* p) {
    return (unsigned)__cvta_generic_to_shared(p);
}
__device__ __forceinline__ void cpa16(unsigned s, const void* g) {
    asm volatile("cp.async.cg.shared.global [%0], [%1], 16;\n" :: "r"(s), "l"(g));
}

// ---------------- fused conv + GEMM + attention-dot epilogue ----------------
// grid 125 (32 rows each), block 256. Double-buffered cp.async pipeline.
// smem layout (floats):
#define SX0 0
#define SX1 15360
#define SB0 30720
#define SB1 34816
#define SAS 38912
#define SCW 39168
#define SMEM_FLOATS 39192

__global__ void __launch_bounds__(256) k_convgemm(
    const float* __restrict__ x,
    const float* __restrict__ cjw, const float* __restrict__ cjb,
    const float* __restrict__ cj2w, const float* __restrict__ cj2b,
    const float* __restrict__ W1, const float* __restrict__ b1,
    const float* __restrict__ att1f) {
    extern __shared__ float sm[];
    int t = threadIdx.x;
    int n0 = blockIdx.x * 32;
    int warp = t >> 5, lane = t & 31;
    int rowbase = warp * 4;

    // stage conv weights into smem
    if (t < 4) sm[SCW + t] = cjw[t];
    if (t < 15) sm[SCW + 4 + t] = cj2w[t];
    if (t == 0) {
        float ws = 0.f;
        for (int k = 0; k < 15; k++) ws += cj2w[k];
        sm[SCW + 19] = cjb[0] * ws + cj2b[0];
    }

    // ---- async copy issuer for tile -> buffer ----
    auto issue = [&](int tile, int buf) {
        float* xb = sm + (buf ? SX1 : SX0);
        float* bb = sm + (buf ? SB1 : SB0);
#pragma unroll
        for (int r = 0; r < 15; r++) {
            int chunk = t + r * 256;          // 0..3839
            int rowch = chunk / 30;           // 0..127
            int ofs = chunk - rowch * 30;     // 0..29 (16B units)
            int c = rowch >> 5, row = rowch & 31;
            const float* g = x + ((size_t)(n0 + row) * 4 + c) * LL + tile * 120 + ofs * 4;
            cpa16(su32(xb + ((c << 5) + row) * 120 + ofs * 4), g);
        }
#pragma unroll
        for (int r = 0; r < 4; r++) {
            int chunk = t + r * 256;          // 0..1023
            int k = chunk >> 7, col4 = (chunk & 127) * 4;
            const float* g = W1 + (size_t)(tile * 8 + k) * FDIM + col4;
            cpa16(su32(bb + k * 512 + col4), g);
        }
        asm volatile("cp.async.commit_group;\n");
    };

    issue(0, 0);
    __syncthreads();

    // conv weights to registers (persist across loop)
    float cwv[4], c2[15], cst;
#pragma unroll
    for (int c = 0; c < 4; c++) cwv[c] = sm[SCW + c];
#pragma unroll
    for (int k = 0; k < 15; k++) c2[k] = sm[SCW + 4 + k];
    cst = sm[SCW + 19];

    unsigned long long acc[4][8];
#pragma unroll
    for (int i = 0; i < 4; i++)
#pragma unroll
        for (int j = 0; j < 8; j++) acc[i][j] = 0ull;

    int crow = t >> 3, cwin = t & 7;

    for (int tile = 0; tile < 125; tile++) {
        int buf = tile & 1;
        if (tile < 124) {
            issue(tile + 1, buf ^ 1);
            asm volatile("cp.async.wait_group 1;\n");
        } else {
            asm volatile("cp.async.wait_group 0;\n");
        }
        __syncthreads();

        // conv: 256 threads -> 32 rows x 8 windows
        {
            const float* xb = sm + (buf ? SX1 : SX0);
            float hv = 0.f;
#pragma unroll
            for (int c = 0; c < 4; c++) {
                const float* p = xb + ((c << 5) + crow) * 120 + cwin * 15;
                float s0 = 0.f;
#pragma unroll
                for (int k = 0; k < 15; k++) s0 += c2[k] * p[k];
                hv += cwv[c] * s0;
            }
            sm[SAS + cwin * 32 + crow] = hv + cst;
        }
        __syncthreads();

        // gemm: 8 k-steps, thread tile 4 rows x (4 segs x 4 cols)
        const float* bb = sm + (buf ? SB1 : SB0);
#pragma unroll
        for (int k = 0; k < 8; k++) {
            float4 av = *(const float4*)(sm + SAS + k * 32 + rowbase);
            unsigned long long a0 = packrep(av.x), a1 = packrep(av.y);
            unsigned long long a2 = packrep(av.z), a3 = packrep(av.w);
#pragma unroll
            for (int seg = 0; seg < 4; seg++) {
                ulonglong2 bv = *(const ulonglong2*)(bb + k * 512 + seg * 128 + lane * 4);
                fma2(acc[0][seg * 2], a0, bv.x); fma2(acc[0][seg * 2 + 1], a0, bv.y);
                fma2(acc[1][seg * 2], a1, bv.x); fma2(acc[1][seg * 2 + 1], a1, bv.y);
                fma2(acc[2][seg * 2], a2, bv.x); fma2(acc[2][seg * 2 + 1], a2, bv.y);
                fma2(acc[3][seg * 2], a3, bv.x); fma2(acc[3][seg * 2 + 1], a3, bv.y);
            }
        }
        __syncthreads();
    }

    // epilogue: +b1, store g_xl, fused attention dots g_af
    float4 b1s[4], afw[4];
#pragma unroll
    for (int seg = 0; seg < 4; seg++) {
        int c0 = seg * 128 + lane * 4;
        b1s[seg] = *(const float4*)&b1[c0];
        afw[seg] = *(const float4*)&att1f[c0];
    }
#pragma unroll
    for (int i = 0; i < 4; i++) {
        int m = n0 + rowbase + i;
#pragma unroll
        for (int seg = 0; seg < 4; seg++) {
            int c0 = seg * 128 + lane * 4;
            float2 v0 = unpack2(acc[i][seg * 2]);
            float2 v1 = unpack2(acc[i][seg * 2 + 1]);
            float o0 = v0.x + b1s[seg].x, o1 = v0.y + b1s[seg].y;
            float o2 = v1.x + b1s[seg].z, o3 = v1.y + b1s[seg].w;
            float4 ov = make_float4(o0, o1, o2, o3);
            *(float4*)&g_xl[(size_t)m * FDIM + c0] = ov;
            float v = o0 * afw[seg].x + o1 * afw[seg].y + o2 * afw[seg].z + o3 * afw[seg].w;
            v += __shfl_down_sync(0xffffffffu, v, 8);
            v += __shfl_down_sync(0xffffffffu, v, 4);
            v += __shfl_down_sync(0xffffffffu, v, 2);
            v += __shfl_down_sync(0xffffffffu, v, 1);
            if ((lane & 15) == 0) g_af[m * 8 + seg * 2 + (lane >> 4)] = v;
        }
    }
}

// ---------------- geneflow fc1 + per-node gene attention dots ----------------
__global__ void k_gf(const float* __restrict__ gfin, const float* __restrict__ fc1w,
                     const float* __restrict__ fc1b, const float* __restrict__ att1g) {
    __shared__ float gin[64], gout[64];
    int n = blockIdx.x, t = threadIdx.x;
    gin[t] = gfin[n * 64 + t];
    __syncthreads();
    float acc = fc1b[t];
#pragma unroll 8
    for (int i = 0; i < 64; i++) acc += gin[i] * fc1w[i * GHD + t];
    g_gf[n * GHD + t] = acc;
    gout[t] = acc;
    __syncthreads();
    if (t < HEADS) {
        float a = 0.f;
#pragma unroll 8
        for (int g = 0; g < GHD; g++) a += gout[g] * att1g[t * GHD + g];
        g_ag[n * HEADS + t] = a;
    }
}

// ---------------- CSR build ----------------
__global__ void k_init() {
    int i = blockIdx.x * blockDim.x + threadIdx.x;
    if (i < NN) g_cnt[i] = 1;  // self loop
}
__global__ void k_hist(const int* __restrict__ ei) {
    int e = blockIdx.x * blockDim.x + threadIdx.x;
    if (e < EE) atomicAdd(&g_cnt[ei[EE + e]], 1);
}
__global__ void k_scan() {  // 1 block, 1024 threads, 4 elems each
    __shared__ int sums[1024];
    int tid = threadIdx.x;
    int base = tid * 4;
    int v0 = 0, v1 = 0, v2 = 0, v3 = 0;
    if (base + 0 < NN) v0 = g_cnt[base + 0];
    if (base + 1 < NN) v1 = g_cnt[base + 1];
    if (base + 2 < NN) v2 = g_cnt[base + 2];
    if (base + 3 < NN) v3 = g_cnt[base + 3];
    sums[tid] = v0 + v1 + v2 + v3;
    __syncthreads();
    for (int off = 1; off < 1024; off <<= 1) {
        int add = (tid >= off) ? sums[tid - off] : 0;
        __syncthreads();
        sums[tid] += add;
        __syncthreads();
    }
    int run = tid ? sums[tid - 1] : 0;
    if (base + 0 < NN) { g_rowptr[base + 0] = run; g_cnt[base + 0] = run; run += v0; }
    if (base + 1 < NN) { g_rowptr[base + 1] = run; g_cnt[base + 1] = run; run += v1; }
    if (base + 2 < NN) { g_rowptr[base + 2] = run; g_cnt[base + 2] = run; run += v2; }
    if (base + 3 < NN) { g_rowptr[base + 3] = run; g_cnt[base + 3] = run; run += v3; }
    if (tid == 1023) g_rowptr[NN] = sums[1023];
}
__global__ void k_scatter(const int* __restrict__ ei) {
    int e = blockIdx.x * blockDim.x + threadIdx.x;
    if (e >= ETOT) return;
    int s, d;
    if (e < EE) { s = ei[e]; d = ei[EE + e]; }
    else        { s = d = e - EE; }
    int p = atomicAdd(&g_cnt[d], 1);
    g_srcs[p] = s;
}

// ---------------- layer-1 attention + aggregation + fused epilogue ----------------
__global__ void __launch_bounds__(512) k_agg1(
    const float* __restrict__ bias1f, const float* __restrict__ bias1g,
    const float* __restrict__ W2, const float* __restrict__ b2,
    const float* __restrict__ fc2w, const float* __restrict__ fc2b) {
    __shared__ float afn[8], agn[8], m1s[8], i1s[8], m2s[8], i2s[8];
    __shared__ int   ssrc[128];
    __shared__ float w2s[128 * 8];
    __shared__ float abars[128];
    __shared__ float red[16];

    int n = blockIdx.x, t = threadIdx.x;
    int base = g_rowptr[n];
    int deg  = g_rowptr[n + 1] - base;
    int w = t >> 5, lane = t & 31;

    if (t < 8) { afn[t] = g_af[n * 8 + t]; agn[t] = g_ag[n * 8 + t]; }
    __syncthreads();

    // pass 1: per-head softmax max & sum (warps 0..7 = heads)
    if (w < 8) {
        int h = w;
        float an = afn[h], gn = agn[h];
        float m1 = -1e30f, m2 = -1e30f;
        for (int e = lane; e < deg; e += 32) {
            int s = g_srcs[base + e];
            float v1 = lrelu(an + g_af[s * 8 + h]);
            float v2 = lrelu(gn + g_ag[s * 8 + h]);
            m1 = fmaxf(m1, v1); m2 = fmaxf(m2, v2);
        }
#pragma unroll
        for (int off = 16; off; off >>= 1) {
            m1 = fmaxf(m1, __shfl_xor_sync(0xffffffffu, m1, off));
            m2 = fmaxf(m2, __shfl_xor_sync(0xffffffffu, m2, off));
        }
        float s1 = 0.f, s2 = 0.f;
        for (int e = lane; e < deg; e += 32) {
            int s = g_srcs[base + e];
            float v1 = lrelu(an + g_af[s * 8 + h]);
            float v2 = lrelu(gn + g_ag[s * 8 + h]);
            s1 += __expf(v1 - m1); s2 += __expf(v2 - m2);
        }
#pragma unroll
        for (int off = 16; off; off >>= 1) {
            s1 += __shfl_xor_sync(0xffffffffu, s1, off);
            s2 += __shfl_xor_sync(0xffffffffu, s2, off);
        }
        if (lane == 0) { m1s[h] = m1; i1s[h] = 1.f / s1; m2s[h] = m2; i2s[h] = 1.f / s2; }
    }
    __syncthreads();

    // pass 2: chunked weighted aggregation
    int h = t >> 6, c = t & 63;
    float accf = 0.f, accg = 0.f;
    for (int c0 = 0; c0 < deg; c0 += 128) {
        int clen = min(128, deg - c0);
        if (t < clen) ssrc[t] = g_srcs[base + c0 + t];
        __syncthreads();
        if (t < clen) {
            int s = ssrc[t];
            float ab = 0.f;
#pragma unroll
            for (int hh = 0; hh < 8; hh++) {
                float v1 = lrelu(afn[hh] + g_af[s * 8 + hh]);
                ab += __expf(v1 - m1s[hh]) * i1s[hh];
                float v2 = lrelu(agn[hh] + g_ag[s * 8 + hh]);
                w2s[t * 8 + hh] = __expf(v2 - m2s[hh]) * i2s[hh];
            }
            abars[t] = ab * 0.125f;
        }
        __syncthreads();
        if (h == 0) {
#pragma unroll 4
            for (int e = 0; e < clen; e++) {
                int s = ssrc[e];
                accf += w2s[e * 8] * g_xl[s * FDIM + t];
                accg += abars[e] * g_gf[s * GHD + c];
            }
        } else {
#pragma unroll 4
            for (int e = 0; e < clen; e++) {
                int s = ssrc[e];
                accf += w2s[e * 8 + h] * g_xl[s * FDIM + t];
            }
        }
        __syncthreads();
    }

    // epilogue: relu + h1@W2+b2 ; relu(g)+fc2
    float o = fmaxf(accf + bias1f[t], 0.f);
    float v = o * W2[t];
#pragma unroll
    for (int off = 16; off; off >>= 1) v += __shfl_down_sync(0xffffffffu, v, off);
    if (lane == 0) red[w] = v;
    __syncthreads();
    if (t < 16) {
        float r = red[t];
#pragma unroll
        for (int off = 8; off; off >>= 1) r += __shfl_down_sync(0x0000ffffu, r, off);
        if (t == 0) g_xl2[n] = r + b2[0];
    }
    float gv = 0.f;
    if (t < 64) {
        float g1 = fmaxf(accg + bias1g[t], 0.f);
        gv = g1 * fc2w[t];
#pragma unroll
        for (int off = 16; off; off >>= 1) gv += __shfl_down_sync(0xffffffffu, gv, off);
    }
    __syncthreads();
    if (t < 64 && lane == 0) red[w] = gv;
    __syncthreads();
    if (t == 0) g_gf2[n] = red[0] + red[1] + fc2b[0];
}

// ---------------- layer 2 (heads=1, C=1) + final sigmoid, warp per node ----------------
__global__ void k_agg2(float* __restrict__ out,
                       const float* __restrict__ att2f, const float* __restrict__ att2g,
                       const float* __restrict__ bias2f, const float* __restrict__ bias2g) {
    int gwarp = (blockIdx.x * blockDim.x + threadIdx.x) >> 5;
    int lane = threadIdx.x & 31;
    if (gwarp >= NN) return;
    int n = gwarp;
    float taf = att2f[0], tag = att2g[0];
    int base = g_rowptr[n], deg = g_rowptr[n + 1] - base;
    float xn = g_xl2[n], gn = g_gf2[n];
    float m1 = -1e30f, m2 = -1e30f;
    for (int e = lane; e < deg; e += 32) {
        int s = g_srcs[base + e];
        float v1 = lrelu(taf * (xn + g_xl2[s]));
        float v2 = lrelu(tag * (gn + g_gf2[s]));
        m1 = fmaxf(m1, v1); m2 = fmaxf(m2, v2);
    }
#pragma unroll
    for (int off = 16; off; off >>= 1) {
        m1 = fmaxf(m1, __shfl_xor_sync(0xffffffffu, m1, off));
        m2 = fmaxf(m2, __shfl_xor_sync(0xffffffffu, m2, off));
    }
    float s1 = 0.f, s2 = 0.f, hf = 0.f, hg = 0.f;
    for (int e = lane; e < deg; e += 32) {
        int s = g_srcs[base + e];
        float xs = g_xl2[s], gs = g_gf2[s];
        float v1 = lrelu(taf * (xn + xs));
        float v2 = lrelu(tag * (gn + gs));
        float e1 = __expf(v1 - m1), e2 = __expf(v2 - m2);
        s1 += e1; s2 += e2;
        hf += e2 * xs;
        hg += e1 * gs;
    }
#pragma unroll
    for (int off = 16; off; off >>= 1) {
        s1 += __shfl_xor_sync(0xffffffffu, s1, off);
        s2 += __shfl_xor_sync(0xffffffffu, s2, off);
        hf += __shfl_xor_sync(0xffffffffu, hf, off);
        hg += __shfl_xor_sync(0xffffffffu, hg, off);
    }
    if (lane == 0) {
        float h2  = hf / s2 + bias2f[0];
        float gf3 = hg / s1 + bias2g[0];
        float z = h2 + gf3;
        out[n] = 1.f / (1.f + __expf(-z));
    }
}

// ---------------- launcher: single stream ----------------
extern "C" void kernel_launch(void* const* d_in, const int* in_sizes, int n_in,
                              void* d_out, int out_size) {
    const float* x      = (const float*)d_in[0];
    const float* gfin   = (const float*)d_in[1];
    const int*   ei     = (const int*)d_in[2];
    const float* cjw    = (const float*)d_in[3];
    const float* cjb    = (const float*)d_in[4];
    const float* cj2w   = (const float*)d_in[5];
    const float* cj2b   = (const float*)d_in[6];
    const float* fc1w   = (const float*)d_in[7];
    const float* fc1b   = (const float*)d_in[8];
    const float* fc2w   = (const float*)d_in[9];
    const float* fc2b   = (const float*)d_in[10];
    const float* W1     = (const float*)d_in[11];
    const float* b1     = (const float*)d_in[12];
    const float* att1f  = (const float*)d_in[13];
    const float* att1g  = (const float*)d_in[14];
    const float* bias1f = (const float*)d_in[15];
    const float* bias1g = (const float*)d_in[16];
    const float* W2     = (const float*)d_in[17];
    const float* b2     = (const float*)d_in[18];
    const float* att2f  = (const float*)d_in[19];
    const float* att2g  = (const float*)d_in[20];
    const float* bias2f = (const float*)d_in[21];
    const float* bias2g = (const float*)d_in[22];
    float* out = (float*)d_out;

    static bool attrSet = false;
    if (!attrSet) {
        cudaFuncSetAttribute(k_convgemm, cudaFuncAttributeMaxDynamicSharedMemorySize,
                             SMEM_FLOATS * 4);
        attrSet = true;
    }

    // order chosen so k_convgemm is the 4th launch (ncu capture slot)
    k_init<<<(NN + 255) / 256, 256>>>();
    k_hist<<<(EE + 255) / 256, 256>>>(ei);
    k_scan<<<1, 1024>>>();
    k_convgemm<<<125, 256, SMEM_FLOATS * 4>>>(x, cjw, cjb, cj2w, cj2b, W1, b1, att1f);
    k_scatter<<<(ETOT + 255) / 256, 256>>>(ei);
    k_gf<<<NN, 64>>>(gfin, fc1w, fc1b, att1g);
    k_agg1<<<NN, 512>>>(bias1f, bias1g, W2, b2, fc2w, fc2b);
    k_agg2<<<(NN * 32 + 255) / 256, 256>>>(out, att2f, att2g, bias2f, bias2g);
}